// round 5
// baseline (speedup 1.0000x reference)
#include <cuda_runtime.h>
#include <cuda_bf16.h>

// Problem constants
#define N_SPK 8192
#define M_UTT 10
#define D_EMB 128
#define CLAMP_MIN 1e-6f

// GEMM tiling
#define BM 64
#define BN 64
#define NTHREADS 256
#define NTILES (N_SPK / BN)   // 128 column tiles
#define NBLOCKS (N_SPK / BM)  // 128 row blocks

// Scratch (allocation-free rule: __device__ globals)
__device__ __align__(16) float g_lhat[N_SPK * D_EMB];
__device__ __align__(16) float g_chat[N_SPK * D_EMB];
__device__ float g_acc;

// packed fp32x2 FMA: acc.lo += a.lo*b.lo ; acc.hi += a.hi*b.hi
#define FMA2(acc, a, b) \
    asm("fma.rn.f32x2 %0, %1, %2, %0;" : "+l"(acc) : "l"(a), "l"(b))

// ---------------------------------------------------------------------------
// Kernel 1: centroids + normalization.
// One block per speaker, 128 threads (one per embedding dim).
// ---------------------------------------------------------------------------
__global__ void __launch_bounds__(128) prep_kernel(const float* __restrict__ x) {
    const int n = blockIdx.x;
    const int d = threadIdx.x;
    const float* xs = x + n * (M_UTT * D_EMB);

    float c = 0.f;
#pragma unroll
    for (int m = 0; m < M_UTT; m++) c += xs[m * D_EMB + d];
    c *= (1.0f / (float)M_UTT);
    float l = xs[(M_UTT - 1) * D_EMB + d];

    // block reduction of c*c and l*l (4 warps)
    float sc = c * c, sl = l * l;
#pragma unroll
    for (int o = 16; o; o >>= 1) {
        sc += __shfl_xor_sync(0xffffffffu, sc, o);
        sl += __shfl_xor_sync(0xffffffffu, sl, o);
    }
    __shared__ float red[8];
    const int wid = d >> 5, lane = d & 31;
    if (lane == 0) { red[wid] = sc; red[4 + wid] = sl; }
    __syncthreads();
    const float tc = red[0] + red[1] + red[2] + red[3];
    const float tl = red[4] + red[5] + red[6] + red[7];

    g_chat[n * D_EMB + d] = c * rsqrtf(tc);
    g_lhat[n * D_EMB + d] = l * rsqrtf(tl);

    if (n == 0 && d == 0) g_acc = 0.f;   // re-zeroed on every graph replay
}

// ---------------------------------------------------------------------------
// Kernel 2: fused cosine-GEMM + online logsumexp + diagonal capture.
// Grid: 128 blocks (one per 64-row stripe). Each block sweeps all 8192 cols.
// Smem: As (64x128 fp32, swizzled) + Bs (64x128 fp32, swizzled) = 64 KB.
// Each thread owns a 4x4 micro-tile; inner k-loop steps by 4 using
// LDS.128 (ulonglong2) feeding packed fp32x2 FMAs.
// ---------------------------------------------------------------------------
__global__ void __launch_bounds__(NTHREADS, 1) gemm_lse_kernel(
    const float* __restrict__ wp, const float* __restrict__ bp) {
    extern __shared__ float smem[];
    float* As = smem;               // 64*128 floats
    float* Bs = smem + BM * D_EMB;  // 64*128 floats
    float4* As4 = (float4*)As;
    float4* Bs4 = (float4*)Bs;
    const ulonglong2* As8 = (const ulonglong2*)As;
    const ulonglong2* Bs8 = (const ulonglong2*)Bs;

    const int tid = threadIdx.x;
    const int tx = tid & 15;        // column group (4 cols each)
    const int ty = tid >> 4;        // row group (4 rows each)
    const int rowBase = blockIdx.x * BM;

    const float w = *wp, b = *bp;
    const float LOG2E = 1.44269504f;
    const float wl = w * LOG2E, bl = b * LOG2E;

    // Load the A stripe once (persists across all column tiles).
    // Swizzle: 16B-chunk index j stored at j ^ ((row>>2)&7).
    const float4* lhat4 = (const float4*)g_lhat;
#pragma unroll
    for (int p = 0; p < 8; p++) {
        int idx = p * NTHREADS + tid;
        int r = idx >> 5, j = idx & 31;
        As4[r * 32 + (j ^ ((r >> 2) & 7))] = lhat4[(rowBase + r) * 32 + j];
    }

    float rs[4] = {0.f, 0.f, 0.f, 0.f};                        // row exp-sums
    float dg[4] = {-1e30f, -1e30f, -1e30f, -1e30f};            // diag logits
    const float4* chat4 = (const float4*)g_chat;
    const int tyx = ty & 7;
    const int txx = tx & 7;

    for (int t = 0; t < NTILES; t++) {
        __syncthreads();   // previous tile's reads of Bs must be done
#pragma unroll
        for (int p = 0; p < 8; p++) {
            int idx = p * NTHREADS + tid;
            int c = idx >> 5, j = idx & 31;
            Bs4[c * 32 + (j ^ ((c >> 2) & 7))] = chat4[(t * BN + c) * 32 + j];
        }
        __syncthreads();

        unsigned long long acc[16];
#pragma unroll
        for (int q = 0; q < 16; q++) acc[q] = 0ull;

#pragma unroll 4
        for (int kk = 0; kk < 32; kk++) {   // 32 chunks of 4 k-values
            ulonglong2 Af[4], Bf[4];
#pragma unroll
            for (int i = 0; i < 4; i++)
                Af[i] = As8[(ty * 4 + i) * 32 + (kk ^ tyx)];
#pragma unroll
            for (int j = 0; j < 4; j++)
                Bf[j] = Bs8[(tx * 4 + j) * 32 + (kk ^ txx)];
#pragma unroll
            for (int i = 0; i < 4; i++)
#pragma unroll
                for (int j = 0; j < 4; j++) {
                    FMA2(acc[i * 4 + j], Af[i].x, Bf[j].x);
                    FMA2(acc[i * 4 + j], Af[i].y, Bf[j].y);
                }
        }

        // Epilogue: cos -> clamp -> exp(w*cos+b) accumulated per row.
        const bool diagTile = (t == blockIdx.x);
#pragma unroll
        for (int i = 0; i < 4; i++) {
#pragma unroll
            for (int j = 0; j < 4; j++) {
                float2 v = *(float2*)&acc[i * 4 + j];
                float cs = v.x + v.y;
                cs = fmaxf(cs, CLAMP_MIN);
                rs[i] += exp2f(fmaf(cs, wl, bl));
                if (diagTile && (tx * 4 + j == ty * 4 + i))
                    dg[i] = fmaf(cs, w, b);
            }
        }
    }

    // Reduce across the 16 tx lanes (same 16-lane half-warp for a given ty).
#pragma unroll
    for (int i = 0; i < 4; i++) {
#pragma unroll
        for (int o = 1; o < 16; o <<= 1) {
            rs[i] += __shfl_xor_sync(0xffffffffu, rs[i], o);
            dg[i] = fmaxf(dg[i], __shfl_xor_sync(0xffffffffu, dg[i], o));
        }
    }

    __syncthreads();   // everyone past the k-loop before smem is reused
    if (tx == 0) {
#pragma unroll
        for (int i = 0; i < 4; i++)
            smem[ty * 4 + i] = logf(rs[i]) - dg[i];   // lse_n - logit_nn (b cancels exactly)
    }
    __syncthreads();
    if (tid == 0) {
        float s = 0.f;
#pragma unroll
        for (int i = 0; i < BM; i++) s += smem[i];
        atomicAdd(&g_acc, s);
    }
}

// ---------------------------------------------------------------------------
// Kernel 3: finalize the scalar loss.
// ---------------------------------------------------------------------------
__global__ void final_kernel(float* __restrict__ out) {
    out[0] = g_acc * (1.0f / (float)N_SPK);
}

extern "C" void kernel_launch(void* const* d_in, const int* in_sizes, int n_in,
                              void* d_out, int out_size) {
    const float* x = (const float*)d_in[0];
    const float* w = (const float*)d_in[1];
    const float* b = (const float*)d_in[2];
    float* out = (float*)d_out;
    (void)in_sizes; (void)n_in; (void)out_size;

    // 64 KB dynamic smem for the GEMM kernel (idempotent; not a stream op,
    // legal under graph capture).
    cudaFuncSetAttribute(gemm_lse_kernel,
                         cudaFuncAttributeMaxDynamicSharedMemorySize,
                         2 * BM * D_EMB * (int)sizeof(float));

    prep_kernel<<<N_SPK, D_EMB>>>(x);
    gemm_lse_kernel<<<NBLOCKS, NTHREADS, 2 * BM * D_EMB * sizeof(float)>>>(w, b);
    final_kernel<<<1, 1>>>(out);
}

// round 7
// speedup vs baseline: 4.8448x; 4.8448x over previous
#include <cuda_runtime.h>
#include <cstdint>

// ---------------- problem constants ----------------
#define N_SPK 8192
#define M_UTT 10
#define D_EMB 128
#define CLAMP_MIN 1e-6f

// ---------------- gemm tiling ----------------
#define TM 128                       // rows per CTA
#define TN 128                       // cols per tile
#define COLS_PER_CTA 4096            // grid.x = 2 column halves
#define NTILES (COLS_PER_CTA / TN)   // 32
#define GTHREADS 256                 // 8 warps: warp tile 32(M) x 64(N)

#define TILE_BYTES (128 * 512)       // 64 KB (128 rows x 512B)
#define SMEM_TOTAL (3 * TILE_BYTES)  // A + B double buffer

// ---------------- device scratch ----------------
__device__ __align__(16) float g_lhat[N_SPK * D_EMB];   // tf32-rounded
__device__ __align__(16) float g_chat[N_SPK * D_EMB];   // tf32-rounded
__device__ float g_part[2][N_SPK];
__device__ float g_diag[N_SPK];

// ---------------- helpers ----------------
__device__ __forceinline__ uint32_t smem_u32(const void* p) {
    uint32_t a;
    asm("{ .reg .u64 t; cvta.to.shared.u64 t, %1; cvt.u32.u64 %0, t; }" : "=r"(a) : "l"(p));
    return a;
}
__device__ __forceinline__ void cp16(uint32_t dst, const void* src) {
    asm volatile("cp.async.cg.shared.global [%0], [%1], 16;" :: "r"(dst), "l"(src) : "memory");
}
#define CP_COMMIT() asm volatile("cp.async.commit_group;" ::: "memory")
#define CP_WAIT0()  asm volatile("cp.async.wait_group 0;" ::: "memory")

__device__ __forceinline__ void mma_tf32(float4& c, uint32_t a0, uint32_t a1,
                                         uint32_t a2, uint32_t a3,
                                         uint32_t b0, uint32_t b1) {
    asm volatile(
        "mma.sync.aligned.m16n8k8.row.col.f32.tf32.tf32.f32 "
        "{%0,%1,%2,%3}, {%4,%5,%6,%7}, {%8,%9}, {%0,%1,%2,%3};"
        : "+f"(c.x), "+f"(c.y), "+f"(c.z), "+f"(c.w)
        : "r"(a0), "r"(a1), "r"(a2), "r"(a3), "r"(b0), "r"(b1));
}

__device__ __forceinline__ float ex2f(float x) {
    float r; asm("ex2.approx.ftz.f32 %0, %1;" : "=f"(r) : "f"(x)); return r;
}
__device__ __forceinline__ float lg2f(float x) {
    float r; asm("lg2.approx.f32 %0, %1;" : "=f"(r) : "f"(x)); return r;
}
__device__ __forceinline__ float tf32r(float x) {
    uint32_t b; asm("cvt.rna.tf32.f32 %0, %1;" : "=r"(b) : "f"(x));
    return __uint_as_float(b);
}

// ---------------------------------------------------------------------------
// Kernel 1: centroids + normalization + tf32 rounding.
// ---------------------------------------------------------------------------
__global__ void __launch_bounds__(128) prep_kernel(const float* __restrict__ x) {
    const int n = blockIdx.x, d = threadIdx.x;
    const float* xs = x + n * (M_UTT * D_EMB);
    float c = 0.f;
#pragma unroll
    for (int m = 0; m < M_UTT; m++) c += xs[m * D_EMB + d];
    c *= (1.0f / (float)M_UTT);
    float l = xs[(M_UTT - 1) * D_EMB + d];

    float sc = c * c, sl = l * l;
#pragma unroll
    for (int o = 16; o; o >>= 1) {
        sc += __shfl_xor_sync(0xffffffffu, sc, o);
        sl += __shfl_xor_sync(0xffffffffu, sl, o);
    }
    __shared__ float red[8];
    const int wid = d >> 5, lane = d & 31;
    if (lane == 0) { red[wid] = sc; red[4 + wid] = sl; }
    __syncthreads();
    const float tc = red[0] + red[1] + red[2] + red[3];
    const float tl = red[4] + red[5] + red[6] + red[7];

    g_chat[n * D_EMB + d] = tf32r(c * rsqrtf(tc));
    g_lhat[n * D_EMB + d] = tf32r(l * rsqrtf(tl));
}

// ---------------------------------------------------------------------------
// Kernel 2: mma.sync tf32 GEMM + fused exp/row-sum epilogue (register-resident).
// Grid (2, 64), 256 threads. Smem: A (64KB) + B double buffer (2x64KB).
// Swizzle: 16B chunk j of row r stored at j ^ (r & 7).
// ---------------------------------------------------------------------------
__global__ void __launch_bounds__(GTHREADS, 1) gemm_lse_kernel(
    const float* __restrict__ wp, const float* __restrict__ bp) {
    extern __shared__ char smem[];
    const uint32_t sb = smem_u32(smem);

    const int tid = threadIdx.x;
    const int wid = tid >> 5, lane = tid & 31;
    const int warp_m = wid >> 1;          // 0..3 : 32-row stripe
    const int warp_n = wid & 1;           // 0..1 : 64-col stripe
    const int laneSw = lane >> 2;         // fragment group id (0..7)
    const int laneC = lane & 3;           // fragment thread-in-group (0..3)

    const int h = blockIdx.x;
    const int rb = blockIdx.y;
    const int rowBase = rb * TM;
    const int colBase = h * COLS_PER_CTA;
    const int tdiag = ((rb >> 5) == h) ? (rb & 31) : -1;

    const float w = *wp, b = *bp;
    const float LOG2E = 1.44269504f;
    const float wl = w * LOG2E, bl = b * LOG2E;

    // ---- async-load A stripe + B tile 0 ----
    const float4* A4 = (const float4*)g_lhat;
    const float4* B4 = (const float4*)g_chat;
#pragma unroll
    for (int p = 0; p < 16; p++) {
        int idx = p * GTHREADS + tid;
        int r = idx >> 5, j = idx & 31;
        uint32_t doff = (uint32_t)(r * 512 + (j ^ (r & 7)) * 16);
        cp16(sb + doff, &A4[(rowBase + r) * 32 + j]);
        cp16(sb + TILE_BYTES + doff, &B4[(colBase + r) * 32 + j]);
    }
    CP_COMMIT();
    CP_WAIT0();
    __syncthreads();

    // per-thread invariant offsets (bytes)
    const uint32_t aRow = sb + (uint32_t)((warp_m * 32 + laneSw) * 512);
    const uint32_t bRowRel = (uint32_t)((warp_n * 64 + laneSw) * 512);
    const uint32_t cOff = (uint32_t)(laneC * 4);

    float4 acc[2][8];
    float rs[4] = {0.f, 0.f, 0.f, 0.f};   // [i*2 + half] row partial exp-sums

    for (int t = 0; t < NTILES; t++) {
        const uint32_t bBuf = sb + TILE_BYTES * (1 + (t & 1));

        // prefetch next B tile into the other buffer (overlaps k-loop)
        if (t + 1 < NTILES) {
            const int nb = t + 1;
#pragma unroll
            for (int p = 0; p < 16; p++) {
                int idx = p * GTHREADS + tid;
                int r = idx >> 5, j = idx & 31;
                uint32_t doff = (uint32_t)(r * 512 + (j ^ (r & 7)) * 16);
                cp16(sb + TILE_BYTES * (1 + (nb & 1)) + doff,
                     &B4[(colBase + nb * TN + r) * 32 + j]);
            }
            CP_COMMIT();
        }

#pragma unroll
        for (int i = 0; i < 2; i++)
#pragma unroll
            for (int j = 0; j < 8; j++) acc[i][j] = make_float4(0.f, 0.f, 0.f, 0.f);

        // ---- k-loop: 16 steps of k=8 ----
#pragma unroll
        for (int ks = 0; ks < 16; ks++) {
            const uint32_t off0 = (uint32_t)(((2 * ks) ^ laneSw) * 16) + cOff;
            const uint32_t off1 = (uint32_t)(((2 * ks + 1) ^ laneSw) * 16) + cOff;

            uint32_t a[2][4];
#pragma unroll
            for (int i = 0; i < 2; i++) {
                const uint32_t base = aRow + (uint32_t)(i * 16 * 512);
                asm volatile("ld.shared.b32 %0, [%1];" : "=r"(a[i][0]) : "r"(base + off0));
                asm volatile("ld.shared.b32 %0, [%1];" : "=r"(a[i][1]) : "r"(base + 8 * 512 + off0));
                asm volatile("ld.shared.b32 %0, [%1];" : "=r"(a[i][2]) : "r"(base + off1));
                asm volatile("ld.shared.b32 %0, [%1];" : "=r"(a[i][3]) : "r"(base + 8 * 512 + off1));
            }
            uint32_t bf[8][2];
#pragma unroll
            for (int j = 0; j < 8; j++) {
                const uint32_t base = bBuf + bRowRel + (uint32_t)(j * 8 * 512);
                asm volatile("ld.shared.b32 %0, [%1];" : "=r"(bf[j][0]) : "r"(base + off0));
                asm volatile("ld.shared.b32 %0, [%1];" : "=r"(bf[j][1]) : "r"(base + off1));
            }
#pragma unroll
            for (int i = 0; i < 2; i++)
#pragma unroll
                for (int j = 0; j < 8; j++)
                    mma_tf32(acc[i][j], a[i][0], a[i][1], a[i][2], a[i][3],
                             bf[j][0], bf[j][1]);
        }

        // ---- epilogue: exp from registers ----
        const bool isDiag = (t == tdiag);
#pragma unroll
        for (int i = 0; i < 2; i++) {
            const int r0 = warp_m * 32 + i * 16 + laneSw;   // local row (+0/+8)
#pragma unroll
            for (int j = 0; j < 8; j++) {
                const int c0 = warp_n * 64 + j * 8 + laneC * 2;  // local col (+0/+1)
                float4 v = acc[i][j];
                float e0 = fmaxf(v.x, CLAMP_MIN);
                float e1 = fmaxf(v.y, CLAMP_MIN);
                float e2 = fmaxf(v.z, CLAMP_MIN);
                float e3 = fmaxf(v.w, CLAMP_MIN);
                rs[i * 2 + 0] += ex2f(fmaf(e0, wl, bl)) + ex2f(fmaf(e1, wl, bl));
                rs[i * 2 + 1] += ex2f(fmaf(e2, wl, bl)) + ex2f(fmaf(e3, wl, bl));
                if (isDiag) {
                    if (r0 == c0)         g_diag[rowBase + r0] = fmaf(e0, w, b);
                    if (r0 == c0 + 1)     g_diag[rowBase + r0] = fmaf(e1, w, b);
                    if (r0 + 8 == c0)     g_diag[rowBase + r0 + 8] = fmaf(e2, w, b);
                    if (r0 + 8 == c0 + 1) g_diag[rowBase + r0 + 8] = fmaf(e3, w, b);
                }
            }
        }

        if (t + 1 < NTILES) CP_WAIT0();
        __syncthreads();
    }

    // ---- reduce rs across laneC (same rows) then across the 2 N-warps ----
#pragma unroll
    for (int q = 0; q < 4; q++) {
        rs[q] += __shfl_xor_sync(0xffffffffu, rs[q], 1);
        rs[q] += __shfl_xor_sync(0xffffffffu, rs[q], 2);
    }
    float* red = (float*)smem;   // reuse A smem (all reads done)
    if (warp_n == 0 && laneC == 0) {
#pragma unroll
        for (int i = 0; i < 2; i++) {
            red[warp_m * 32 + i * 16 + laneSw] = rs[i * 2 + 0];
            red[warp_m * 32 + i * 16 + 8 + laneSw] = rs[i * 2 + 1];
        }
    }
    __syncthreads();
    if (warp_n == 1 && laneC == 0) {
#pragma unroll
        for (int i = 0; i < 2; i++) {
            int r = warp_m * 32 + i * 16 + laneSw;
            g_part[h][rowBase + r] = red[r] + rs[i * 2 + 0];
            g_part[h][rowBase + r + 8] = red[r + 8] + rs[i * 2 + 1];
        }
    }
}

// ---------------------------------------------------------------------------
// Kernel 3: loss = mean(log(rowsum) - diag_logit)
// ---------------------------------------------------------------------------
__global__ void __launch_bounds__(1024) final_kernel(float* __restrict__ out) {
    const int tid = threadIdx.x;
    const float LN2 = 0.69314718056f;
    float s = 0.f;
#pragma unroll
    for (int i = 0; i < 8; i++) {
        int r = tid + i * 1024;
        float sum = g_part[0][r] + g_part[1][r];
        s += lg2f(sum) * LN2 - g_diag[r];
    }
#pragma unroll
    for (int o = 16; o; o >>= 1) s += __shfl_xor_sync(0xffffffffu, s, o);
    __shared__ float sred[32];
    const int wid = tid >> 5, lane = tid & 31;
    if (lane == 0) sred[wid] = s;
    __syncthreads();
    if (wid == 0) {
        float v = sred[lane];
#pragma unroll
        for (int o = 16; o; o >>= 1) v += __shfl_xor_sync(0xffffffffu, v, o);
        if (lane == 0) out[0] = v * (1.0f / (float)N_SPK);
    }
}

extern "C" void kernel_launch(void* const* d_in, const int* in_sizes, int n_in,
                              void* d_out, int out_size) {
    const float* x = (const float*)d_in[0];
    const float* w = (const float*)d_in[1];
    const float* b = (const float*)d_in[2];
    float* out = (float*)d_out;
    (void)in_sizes; (void)n_in; (void)out_size;

    cudaFuncSetAttribute(gemm_lse_kernel,
                         cudaFuncAttributeMaxDynamicSharedMemorySize, SMEM_TOTAL);

    prep_kernel<<<N_SPK, D_EMB>>>(x);
    gemm_lse_kernel<<<dim3(2, 64), GTHREADS, SMEM_TOTAL>>>(w, b);
    final_kernel<<<1, 1024>>>(out);
}

// round 8
// speedup vs baseline: 7.7335x; 1.5963x over previous
#include <cuda_runtime.h>
#include <cuda_bf16.h>
#include <cstdint>

// ---------------- problem constants ----------------
#define N_SPK 8192
#define M_UTT 10
#define D_EMB 128
#define CLAMP_MIN 1e-6f

// ---------------- gemm tiling ----------------
#define TM 128                       // rows per CTA
#define TN 128                       // cols per tile
#define COLS_PER_CTA 4096            // grid.x = 2 column halves
#define NTILES (COLS_PER_CTA / TN)   // 32
#define GTHREADS 256                 // 8 warps: warp tile 32(M) x 64(N)

#define ROW_BYTES 256                // 128 bf16
#define TILE_BYTES (128 * ROW_BYTES) // 32 KB
#define SMEM_TOTAL (3 * TILE_BYTES)  // A + B double buffer = 96 KB

// ---------------- device scratch ----------------
__device__ __align__(16) __nv_bfloat16 g_lhat[N_SPK * D_EMB];
__device__ __align__(16) __nv_bfloat16 g_chat[N_SPK * D_EMB];
__device__ float g_part[2][N_SPK];
__device__ float g_diag[N_SPK];

// ---------------- helpers ----------------
__device__ __forceinline__ uint32_t smem_u32(const void* p) {
    uint32_t a;
    asm("{ .reg .u64 t; cvta.to.shared.u64 t, %1; cvt.u32.u64 %0, t; }" : "=r"(a) : "l"(p));
    return a;
}
__device__ __forceinline__ void cp16(uint32_t dst, const void* src) {
    asm volatile("cp.async.cg.shared.global [%0], [%1], 16;" :: "r"(dst), "l"(src) : "memory");
}
#define CP_COMMIT() asm volatile("cp.async.commit_group;" ::: "memory")
#define CP_WAIT0()  asm volatile("cp.async.wait_group 0;" ::: "memory")

__device__ __forceinline__ void mma_bf16(float4& c, uint32_t a0, uint32_t a1,
                                         uint32_t a2, uint32_t a3,
                                         uint32_t b0, uint32_t b1) {
    asm volatile(
        "mma.sync.aligned.m16n8k16.row.col.f32.bf16.bf16.f32 "
        "{%0,%1,%2,%3}, {%4,%5,%6,%7}, {%8,%9}, {%0,%1,%2,%3};"
        : "+f"(c.x), "+f"(c.y), "+f"(c.z), "+f"(c.w)
        : "r"(a0), "r"(a1), "r"(a2), "r"(a3), "r"(b0), "r"(b1));
}

__device__ __forceinline__ float ex2f(float x) {
    float r; asm("ex2.approx.ftz.f32 %0, %1;" : "=f"(r) : "f"(x)); return r;
}
__device__ __forceinline__ float lg2f(float x) {
    float r; asm("lg2.approx.f32 %0, %1;" : "=f"(r) : "f"(x)); return r;
}
__device__ __forceinline__ uint32_t lds32(uint32_t a) {
    uint32_t v; asm volatile("ld.shared.b32 %0, [%1];" : "=r"(v) : "r"(a)); return v;
}

// ---------------------------------------------------------------------------
// Kernel 1: centroids + normalization + bf16 rounding.
// One warp per speaker, lane covers 4 dims via float4. Grid 1024 x 256.
// ---------------------------------------------------------------------------
__global__ void __launch_bounds__(256) prep_kernel(const float* __restrict__ x) {
    const int lane = threadIdx.x & 31;
    const int n = blockIdx.x * 8 + (threadIdx.x >> 5);
    const float4* xs = (const float4*)(x + (size_t)n * (M_UTT * D_EMB));

    float4 c = make_float4(0.f, 0.f, 0.f, 0.f);
    float4 l;
#pragma unroll
    for (int m = 0; m < M_UTT; m++) {
        float4 v = xs[m * 32 + lane];
        c.x += v.x; c.y += v.y; c.z += v.z; c.w += v.w;
        if (m == M_UTT - 1) l = v;
    }
    c.x *= 0.1f; c.y *= 0.1f; c.z *= 0.1f; c.w *= 0.1f;

    float sc = c.x * c.x + c.y * c.y + c.z * c.z + c.w * c.w;
    float sl = l.x * l.x + l.y * l.y + l.z * l.z + l.w * l.w;
#pragma unroll
    for (int o = 16; o; o >>= 1) {
        sc += __shfl_xor_sync(0xffffffffu, sc, o);
        sl += __shfl_xor_sync(0xffffffffu, sl, o);
    }
    const float rc = rsqrtf(sc), rl = rsqrtf(sl);

    __nv_bfloat162 c01 = __floats2bfloat162_rn(c.x * rc, c.y * rc);
    __nv_bfloat162 c23 = __floats2bfloat162_rn(c.z * rc, c.w * rc);
    __nv_bfloat162 l01 = __floats2bfloat162_rn(l.x * rl, l.y * rl);
    __nv_bfloat162 l23 = __floats2bfloat162_rn(l.z * rl, l.w * rl);

    uint2 cv, lv;
    cv.x = *(uint32_t*)&c01; cv.y = *(uint32_t*)&c23;
    lv.x = *(uint32_t*)&l01; lv.y = *(uint32_t*)&l23;
    ((uint2*)(g_chat + n * D_EMB))[lane] = cv;
    ((uint2*)(g_lhat + n * D_EMB))[lane] = lv;
}

// ---------------------------------------------------------------------------
// Kernel 2: mma.sync bf16 GEMM + fused exp/row-sum epilogue.
// Grid (2, 64), 256 threads. Smem: A (32KB) + B double buffer (2x32KB).
// Swizzle: 16B chunk c of row r stored at c ^ (r & 7).
// ---------------------------------------------------------------------------
__global__ void __launch_bounds__(GTHREADS, 1) gemm_lse_kernel(
    const float* __restrict__ wp, const float* __restrict__ bp) {
    extern __shared__ char smem[];
    const uint32_t sb = smem_u32(smem);

    const int tid = threadIdx.x;
    const int wid = tid >> 5, lane = tid & 31;
    const int warp_m = wid >> 1;          // 0..3 : 32-row stripe
    const int warp_n = wid & 1;           // 0..1 : 64-col stripe
    const int gid = lane >> 2;            // fragment group id (0..7)
    const int tid4 = lane & 3;

    const int h = blockIdx.x;
    const int rb = blockIdx.y;
    const int rowBase = rb * TM;
    const int colBase = h * COLS_PER_CTA;
    const int tdiag = ((rb >> 5) == h) ? (rb & 31) : -1;

    const float w = *wp, b = *bp;
    const float LOG2E = 1.44269504f;
    const float wl = w * LOG2E, bl = b * LOG2E;

    // ---- async-load A stripe + B tile 0 (each 32KB = 2048 16B chunks) ----
    const float4* A4 = (const float4*)g_lhat;   // 16 chunks per 256B row
    const float4* B4 = (const float4*)g_chat;
#pragma unroll
    for (int p = 0; p < 8; p++) {
        int idx = p * GTHREADS + tid;
        int r = idx >> 4, c = idx & 15;
        uint32_t doff = (uint32_t)(r * ROW_BYTES + ((c ^ (r & 7)) << 4));
        cp16(sb + doff, &A4[(rowBase + r) * 16 + c]);
        cp16(sb + TILE_BYTES + doff, &B4[(colBase + r) * 16 + c]);
    }
    CP_COMMIT();
    CP_WAIT0();
    __syncthreads();

    // per-thread invariant byte offsets
    const uint32_t aRow = sb + (uint32_t)((warp_m * 32 + gid) * ROW_BYTES);
    const uint32_t bRel = (uint32_t)((warp_n * 64 + gid) * ROW_BYTES);
    const uint32_t cOff = (uint32_t)(tid4 * 4);

    float4 acc[2][8];
    float rs[4] = {0.f, 0.f, 0.f, 0.f};

    for (int t = 0; t < NTILES; t++) {
        const uint32_t bBuf = sb + TILE_BYTES * (1 + (t & 1));

        // prefetch next B tile into the other buffer
        if (t + 1 < NTILES) {
            const int nb = t + 1;
#pragma unroll
            for (int p = 0; p < 8; p++) {
                int idx = p * GTHREADS + tid;
                int r = idx >> 4, c = idx & 15;
                uint32_t doff = (uint32_t)(r * ROW_BYTES + ((c ^ (r & 7)) << 4));
                cp16(sb + TILE_BYTES * (1 + (nb & 1)) + doff,
                     &B4[(colBase + nb * TN + r) * 16 + c]);
            }
            CP_COMMIT();
        }

#pragma unroll
        for (int i = 0; i < 2; i++)
#pragma unroll
            for (int j = 0; j < 8; j++) acc[i][j] = make_float4(0.f, 0.f, 0.f, 0.f);

        // ---- k-loop: 8 steps of k=16 (two 16B chunks per row per step) ----
#pragma unroll
        for (int ks = 0; ks < 8; ks++) {
            const uint32_t off0 = (uint32_t)(((2 * ks) ^ gid) << 4) + cOff;
            const uint32_t off1 = (uint32_t)(((2 * ks + 1) ^ gid) << 4) + cOff;

            uint32_t a[2][4];
#pragma unroll
            for (int i = 0; i < 2; i++) {
                const uint32_t base = aRow + (uint32_t)(i * 16 * ROW_BYTES);
                a[i][0] = lds32(base + off0);
                a[i][1] = lds32(base + 8 * ROW_BYTES + off0);
                a[i][2] = lds32(base + off1);
                a[i][3] = lds32(base + 8 * ROW_BYTES + off1);
            }
            uint32_t bf[8][2];
#pragma unroll
            for (int j = 0; j < 8; j++) {
                const uint32_t base = bBuf + bRel + (uint32_t)(j * 8 * ROW_BYTES);
                bf[j][0] = lds32(base + off0);
                bf[j][1] = lds32(base + off1);
            }
#pragma unroll
            for (int i = 0; i < 2; i++)
#pragma unroll
                for (int j = 0; j < 8; j++)
                    mma_bf16(acc[i][j], a[i][0], a[i][1], a[i][2], a[i][3],
                             bf[j][0], bf[j][1]);
        }

        // ---- epilogue: exp from registers ----
        const bool isDiag = (t == tdiag);
#pragma unroll
        for (int i = 0; i < 2; i++) {
            const int r0 = warp_m * 32 + i * 16 + gid;
#pragma unroll
            for (int j = 0; j < 8; j++) {
                const int c0 = warp_n * 64 + j * 8 + tid4 * 2;
                float4 v = acc[i][j];
                float e0 = fmaxf(v.x, CLAMP_MIN);
                float e1 = fmaxf(v.y, CLAMP_MIN);
                float e2 = fmaxf(v.z, CLAMP_MIN);
                float e3 = fmaxf(v.w, CLAMP_MIN);
                rs[i * 2 + 0] += ex2f(fmaf(e0, wl, bl)) + ex2f(fmaf(e1, wl, bl));
                rs[i * 2 + 1] += ex2f(fmaf(e2, wl, bl)) + ex2f(fmaf(e3, wl, bl));
                if (isDiag) {
                    if (r0 == c0)         g_diag[rowBase + r0] = fmaf(e0, w, b);
                    if (r0 == c0 + 1)     g_diag[rowBase + r0] = fmaf(e1, w, b);
                    if (r0 + 8 == c0)     g_diag[rowBase + r0 + 8] = fmaf(e2, w, b);
                    if (r0 + 8 == c0 + 1) g_diag[rowBase + r0 + 8] = fmaf(e3, w, b);
                }
            }
        }

        if (t + 1 < NTILES) CP_WAIT0();
        __syncthreads();
    }

    // ---- reduce rs across tid4 lanes, then across the 2 N-warps ----
#pragma unroll
    for (int q = 0; q < 4; q++) {
        rs[q] += __shfl_xor_sync(0xffffffffu, rs[q], 1);
        rs[q] += __shfl_xor_sync(0xffffffffu, rs[q], 2);
    }
    float* red = (float*)smem;   // reuse A smem
    if (warp_n == 0 && tid4 == 0) {
#pragma unroll
        for (int i = 0; i < 2; i++) {
            red[warp_m * 32 + i * 16 + gid] = rs[i * 2 + 0];
            red[warp_m * 32 + i * 16 + 8 + gid] = rs[i * 2 + 1];
        }
    }
    __syncthreads();
    if (warp_n == 1 && tid4 == 0) {
#pragma unroll
        for (int i = 0; i < 2; i++) {
            int r = warp_m * 32 + i * 16 + gid;
            g_part[h][rowBase + r] = red[r] + rs[i * 2 + 0];
            g_part[h][rowBase + r + 8] = red[r + 8] + rs[i * 2 + 1];
        }
    }
}

// ---------------------------------------------------------------------------
// Kernel 3: loss = mean(log(rowsum) - diag_logit)
// ---------------------------------------------------------------------------
__global__ void __launch_bounds__(1024) final_kernel(float* __restrict__ out) {
    const int tid = threadIdx.x;
    const float LN2 = 0.69314718056f;
    float s = 0.f;
#pragma unroll
    for (int i = 0; i < 8; i++) {
        int r = tid + i * 1024;
        float sum = g_part[0][r] + g_part[1][r];
        s += lg2f(sum) * LN2 - g_diag[r];
    }
#pragma unroll
    for (int o = 16; o; o >>= 1) s += __shfl_xor_sync(0xffffffffu, s, o);
    __shared__ float sred[32];
    const int wid = tid >> 5, lane = tid & 31;
    if (lane == 0) sred[wid] = s;
    __syncthreads();
    if (wid == 0) {
        float v = sred[lane];
#pragma unroll
        for (int o = 16; o; o >>= 1) v += __shfl_xor_sync(0xffffffffu, v, o);
        if (lane == 0) out[0] = v * (1.0f / (float)N_SPK);
    }
}

extern "C" void kernel_launch(void* const* d_in, const int* in_sizes, int n_in,
                              void* d_out, int out_size) {
    const float* x = (const float*)d_in[0];
    const float* w = (const float*)d_in[1];
    const float* b = (const float*)d_in[2];
    float* out = (float*)d_out;
    (void)in_sizes; (void)n_in; (void)out_size;

    cudaFuncSetAttribute(gemm_lse_kernel,
                         cudaFuncAttributeMaxDynamicSharedMemorySize, SMEM_TOTAL);

    prep_kernel<<<N_SPK / 8, 256>>>(x);
    gemm_lse_kernel<<<dim3(2, 64), GTHREADS, SMEM_TOTAL>>>(w, b);
    final_kernel<<<1, 1024>>>(out);
}